// round 1
// baseline (speedup 1.0000x reference)
#include <cuda_runtime.h>
#include <math.h>

#define NN 100000
#define NE 3200000
#define NG 64
#define D 32
#define INF 128

// ---- scratch (static device globals; no allocation) ----
__device__ float g_rhs[NN * D];    // h @ Wn  (gathered over edges)
__device__ float g_self[NN * D];   // h @ Ws
__device__ float g_h[NN * D];      // current node features
__device__ float g_pool[NG * D];   // per-graph sums
__device__ int   g_counts[NN];
__device__ int   g_offs[NN + 1];
__device__ int   g_cursor[NN];
__device__ int   g_csrc[NE];       // CSR (by dst) storing src
__device__ int   g_bsums[256];

// ------------------------------------------------------------------
// init: zero histogram counts + pool accumulator
__global__ void zero_kernel() {
    int i = blockIdx.x * blockDim.x + threadIdx.x;
    int stride = gridDim.x * blockDim.x;
    for (int j = i; j < NN; j += stride) g_counts[j] = 0;
    if (i < NG * D) g_pool[i] = 0.f;
}

// histogram of dst
__global__ void hist_kernel(const int* __restrict__ dst) {
    int i = blockIdx.x * blockDim.x + threadIdx.x;
    if (i < NE) atomicAdd(&g_counts[dst[i]], 1);
}

// exclusive scan (3 kernels): per-block scan, scan of block sums, add base
__global__ void scan_part() {
    __shared__ int sh[512];
    int tid = threadIdx.x;
    int i = blockIdx.x * 512 + tid;
    int v = (i < NN) ? g_counts[i] : 0;
    sh[tid] = v;
    __syncthreads();
    for (int d = 1; d < 512; d <<= 1) {
        int t = (tid >= d) ? sh[tid - d] : 0;
        __syncthreads();
        sh[tid] += t;
        __syncthreads();
    }
    if (i < NN) g_offs[i] = sh[tid] - v;   // block-local exclusive
    if (tid == 511) g_bsums[blockIdx.x] = sh[511];
}

__global__ void scan_sums() {   // 1 thread: 196 block sums
    int acc = 0;
    for (int b = 0; b < 196; b++) { int v = g_bsums[b]; g_bsums[b] = acc; acc += v; }
    g_offs[NN] = acc;           // == NE
}

__global__ void scan_add() {
    int i = blockIdx.x * 512 + threadIdx.x;
    if (i < NN) {
        int o = g_offs[i] + g_bsums[blockIdx.x];
        g_offs[i] = o;
        g_cursor[i] = o;
    }
}

// scatter edges into CSR slots
__global__ void scatter_kernel(const int* __restrict__ src, const int* __restrict__ dst) {
    int i = blockIdx.x * blockDim.x + threadIdx.x;
    if (i < NE) {
        int p = atomicAdd(&g_cursor[dst[i]], 1);
        g_csrc[p] = src[i];
    }
}

// ------------------------------------------------------------------
// Layer 0 GEMM: rhs = x@Wn0, self = x@Ws0   (K=128, 64 outputs fused)
// block = 256 thr: 16 nodes x 16 thr/node, 4 outputs per thread
__global__ void __launch_bounds__(256) gemm0_kernel(const float* __restrict__ x,
                                                    const float* __restrict__ Wn0,
                                                    const float* __restrict__ Ws0) {
    __shared__ float Wsh[INF][64];
    __shared__ float xs[16][INF];
    int tid = threadIdx.x;
    for (int idx = tid; idx < INF * D; idx += 256) {
        int k = idx / D, c = idx % D;
        Wsh[k][c]      = Wn0[idx];
        Wsh[k][c + 32] = Ws0[idx];
    }
    int n0 = blockIdx.x * 16;
    for (int idx = tid; idx < 16 * INF; idx += 256) {
        int nl = idx / INF, k = idx % INF;
        int n = n0 + nl;
        xs[nl][k] = (n < NN) ? x[n * INF + k] : 0.f;
    }
    __syncthreads();
    int nl = tid >> 4, og = tid & 15;
    float a0 = 0.f, a1 = 0.f, a2 = 0.f, a3 = 0.f;
#pragma unroll 8
    for (int k = 0; k < INF; k++) {
        float xv = xs[nl][k];
        float4 w = *(const float4*)&Wsh[k][og * 4];
        a0 = fmaf(xv, w.x, a0); a1 = fmaf(xv, w.y, a1);
        a2 = fmaf(xv, w.z, a2); a3 = fmaf(xv, w.w, a3);
    }
    int n = n0 + nl;
    if (n < NN) {
        float4 r = make_float4(a0, a1, a2, a3);
        if (og < 8) *(float4*)&g_rhs[n * D + og * 4] = r;
        else        *(float4*)&g_self[n * D + (og - 8) * 4] = r;
    }
}

// Layers 1..3 GEMM: same structure, K=32, input = g_h
__global__ void __launch_bounds__(256) gemm_small_kernel(const float* __restrict__ Wn_l,
                                                         const float* __restrict__ Ws_l) {
    __shared__ float Wsh[D][64];
    __shared__ float xs[16][D];
    int tid = threadIdx.x;
    for (int idx = tid; idx < D * D; idx += 256) {
        int k = idx / D, c = idx % D;
        Wsh[k][c]      = Wn_l[idx];
        Wsh[k][c + 32] = Ws_l[idx];
    }
    int n0 = blockIdx.x * 16;
    for (int idx = tid; idx < 16 * D; idx += 256) {
        int nl = idx / D, k = idx % D;
        int n = n0 + nl;
        xs[nl][k] = (n < NN) ? g_h[n * D + k] : 0.f;
    }
    __syncthreads();
    int nl = tid >> 4, og = tid & 15;
    float a0 = 0.f, a1 = 0.f, a2 = 0.f, a3 = 0.f;
#pragma unroll
    for (int k = 0; k < D; k++) {
        float xv = xs[nl][k];
        float4 w = *(const float4*)&Wsh[k][og * 4];
        a0 = fmaf(xv, w.x, a0); a1 = fmaf(xv, w.y, a1);
        a2 = fmaf(xv, w.z, a2); a3 = fmaf(xv, w.w, a3);
    }
    int n = n0 + nl;
    if (n < NN) {
        float4 r = make_float4(a0, a1, a2, a3);
        if (og < 8) *(float4*)&g_rhs[n * D + og * 4] = r;
        else        *(float4*)&g_self[n * D + (og - 8) * 4] = r;
    }
}

// Aggregation: warp per node, lane = dim.  h = relu(sum_{e->n} rhs[src] + bn + self)
__global__ void __launch_bounds__(256) agg_kernel(const float* __restrict__ bn) {
    int w = (blockIdx.x * blockDim.x + threadIdx.x) >> 5;
    int lane = threadIdx.x & 31;
    if (w >= NN) return;
    int beg = g_offs[w], end = g_offs[w + 1];
    float acc = g_self[w * D + lane] + bn[lane];
    int e = beg;
    for (; e + 4 <= end; e += 4) {
        int s0 = g_csrc[e], s1 = g_csrc[e + 1], s2 = g_csrc[e + 2], s3 = g_csrc[e + 3];
        float v0 = g_rhs[s0 * D + lane];
        float v1 = g_rhs[s1 * D + lane];
        float v2 = g_rhs[s2 * D + lane];
        float v3 = g_rhs[s3 * D + lane];
        acc += v0; acc += v1; acc += v2; acc += v3;
    }
    for (; e < end; e++) acc += g_rhs[g_csrc[e] * D + lane];
    g_h[w * D + lane] = fmaxf(acc, 0.f);
}

// Per-graph sum pooling (graph_ids sorted): shared accumulator per block
__global__ void __launch_bounds__(256) pool_kernel(const int* __restrict__ gid) {
    __shared__ float ps[NG * D];
    int tid = threadIdx.x;
    for (int i = tid; i < NG * D; i += 256) ps[i] = 0.f;
    __syncthreads();
    int d = tid & 31;
    int base = blockIdx.x * 1024;
    for (int i = tid >> 5; i < 1024; i += 8) {
        int n = base + i;
        if (n < NN) atomicAdd(&ps[gid[n] * D + d], g_h[n * D + d]);
    }
    __syncthreads();
    for (int i = tid; i < NG * D; i += 256) {
        float v = ps[i];
        if (v != 0.f) atomicAdd(&g_pool[i], v);
    }
}

// Final MLP + softmax, one thread per graph
__global__ void mlp_kernel(const float* __restrict__ Wfc1, const float* __restrict__ bfc1,
                           const float* __restrict__ Wout, const float* __restrict__ bout,
                           float* __restrict__ out) {
    int g = threadIdx.x;
    if (g >= NG) return;
    float hv[D];
#pragma unroll
    for (int k = 0; k < D; k++) hv[k] = g_pool[g * D + k];
    float h2[8];
#pragma unroll
    for (int j = 0; j < 8; j++) {
        float s = bfc1[j];
#pragma unroll
        for (int k = 0; k < D; k++) s = fmaf(hv[k], Wfc1[k * 8 + j], s);
        h2[j] = fmaxf(s, 0.f);
    }
    float o[4];
    float m = -1e30f;
#pragma unroll
    for (int j = 0; j < 4; j++) {
        float s = bout[j];
#pragma unroll
        for (int k = 0; k < 8; k++) s = fmaf(h2[k], Wout[k * 4 + j], s);
        o[j] = fmaxf(s, 0.f);
        if (o[j] > m) m = o[j];
    }
    float e[4]; float sum = 0.f;
#pragma unroll
    for (int j = 0; j < 4; j++) { e[j] = expf(o[j] - m); sum += e[j]; }
#pragma unroll
    for (int j = 0; j < 4; j++) out[g * 4 + j] = e[j] / sum;
}

// ------------------------------------------------------------------
extern "C" void kernel_launch(void* const* d_in, const int* in_sizes, int n_in,
                              void* d_out, int out_size) {
    const float* x    = (const float*)d_in[0];
    const float* Wn0  = (const float*)d_in[1];
    const float* bn0  = (const float*)d_in[2];
    const float* Ws0  = (const float*)d_in[3];
    const float* Wn   = (const float*)d_in[4];   // [3,32,32]
    const float* bn   = (const float*)d_in[5];   // [3,32]
    const float* Ws   = (const float*)d_in[6];   // [3,32,32]
    const float* Wfc1 = (const float*)d_in[7];
    const float* bfc1 = (const float*)d_in[8];
    const float* Wout = (const float*)d_in[9];
    const float* bout = (const float*)d_in[10];
    const int*   src  = (const int*)d_in[11];
    const int*   dst  = (const int*)d_in[12];
    const int*   gid  = (const int*)d_in[13];
    float* out = (float*)d_out;

    // CSR build (per call; reused by all 4 layers)
    zero_kernel<<<512, 256>>>();
    hist_kernel<<<(NE + 255) / 256, 256>>>(dst);
    scan_part<<<196, 512>>>();
    scan_sums<<<1, 1>>>();
    scan_add<<<196, 512>>>();
    scatter_kernel<<<(NE + 255) / 256, 256>>>(src, dst);

    // Layer 0
    gemm0_kernel<<<(NN + 15) / 16, 256>>>(x, Wn0, Ws0);
    agg_kernel<<<(NN * 32 + 255) / 256, 256>>>(bn0);

    // Layers 1..3
    for (int l = 0; l < 3; l++) {
        gemm_small_kernel<<<(NN + 15) / 16, 256>>>(Wn + l * D * D, Ws + l * D * D);
        agg_kernel<<<(NN * 32 + 255) / 256, 256>>>(bn + l * D);
    }

    // Pool + MLP + softmax
    pool_kernel<<<(NN + 1023) / 1024, 256>>>(gid);
    mlp_kernel<<<1, 64>>>(Wfc1, bfc1, Wout, bout, out);
}